// round 13
// baseline (speedup 1.0000x reference)
#include <cuda_runtime.h>
#include <stdint.h>

// SparseActivation: per-row top-k (k=204) by |x| over D=2048, out = x*mask*(D/k).
// ONE WARP PER ROW, no __syncthreads.
//  Pass A: 16 LDG.128/lane (unroll 8); ballot-compact (raw bits, uint16 index)
//          of candidates |v|>=1.45f into per-warp smem (E[nc]~300+-16, checked
//          vs [204,416]).
//  Pass B: register-cached (CPL=13) warp MSB-first bisection on abs bits,
//          early exit (rank==group -> min, rank==1 -> max), REDUX reductions.
//          nc out of range -> exact global-bisect fallback.
//  Pass C (fast, no bit-ties): zero-fill the row with streaming STG.128, then
//          __syncwarp (warp-scope memory ordering; row is warp-private) and
//          scatter the selected candidates from smem. NO global re-read.
//  Pass C (slow: ties at T, or fallback): R11-proven global re-read path with
//          exact lowest-index-first tie ranking.

#define DDIM          2048
#define KSEL          204u
#define WARPS_PER_CTA 8
#define THREADS       (WARPS_PER_CTA * 32)
#define NCHUNK        16          // 16 float4 per lane = 2048 floats per warp
#define CAP           416         // per-warp candidate cap = 13 per lane
#define CPL           13
#define KLO_F         1.45f

static __device__ __forceinline__ uint32_t absbits(float f) {
    return __float_as_uint(f) & 0x7fffffffu;
}

__global__ __launch_bounds__(THREADS)
void sparse_act_kernel(const float* __restrict__ x, float* __restrict__ out)
{
    __shared__ uint32_t rawb[WARPS_PER_CTA][CAP];
    __shared__ uint16_t idxb[WARPS_PER_CTA][CAP];

    const int lane = threadIdx.x & 31;
    const int warp = threadIdx.x >> 5;
    const size_t row = (size_t)blockIdx.x * WARPS_PER_CTA + warp;

    const float4* __restrict__ xr   = reinterpret_cast<const float4*>(x + row * (size_t)DDIM);
    float4* __restrict__       orow = reinterpret_cast<float4*>(out + row * (size_t)DDIM);
    uint32_t* __restrict__     wraw = rawb[warp];
    uint16_t* __restrict__     widx = idxb[warp];

    // ── Pass A: ballot-compact (raw, idx) of candidates (|v| >= KLO_F) ──
    uint32_t base = 0;
#pragma unroll 8
    for (int i = 0; i < NCHUNK; ++i) {
        const float4 v = xr[i * 32 + lane];
        const float vv[4] = { v.x, v.y, v.z, v.w };
#pragma unroll
        for (int j = 0; j < 4; ++j) {
            const bool p = fabsf(vv[j]) >= KLO_F;
            const uint32_t bal = __ballot_sync(0xffffffffu, p);
            const uint32_t off = base + (uint32_t)__popc(bal & ((1u << lane) - 1u));
            if (p && off < CAP) {
                wraw[off] = __float_as_uint(vv[j]);
                widx[off] = (uint16_t)(i * 128 + lane * 4 + j);
            }
            base += (uint32_t)__popc(bal);
        }
    }
    const uint32_t nc = base;
    const bool fastok = (nc >= KSEL && nc <= CAP);

    uint32_t T, need, cntEq;

    if (fastok) {
        // ── Pass B: register-resident candidates, early-exit bisection ──
        uint32_t c[CPL];
#pragma unroll
        for (int j = 0; j < CPL; ++j) {
            const uint32_t idx = (uint32_t)lane + 32u * j;   // < CAP always
            const uint32_t t = wraw[idx] & 0x7fffffffu;      // abs-mask here
            c[j] = (idx < nc) ? t : 0xffffffffu;             // sentinel (never matches)
        }
        int b = 31;
        uint32_t p = 0u, kk = KSEL, g = nc;
        while (true) {
            if (kk == g) {            // take whole group -> T = group min
                uint32_t m = 0xffffffffu;
#pragma unroll
                for (int j = 0; j < CPL; ++j)
                    if ((c[j] >> b) == (p >> b)) m = min(m, c[j]);
                T = __reduce_min_sync(0xffffffffu, m);
                uint32_t e = 0;
#pragma unroll
                for (int j = 0; j < CPL; ++j) e += (c[j] == T) ? 1u : 0u;
                need  = __reduce_add_sync(0xffffffffu, e);
                cntEq = need;
                break;
            }
            if (kk == 1u) {           // T = group max
                uint32_t m = 0u;
#pragma unroll
                for (int j = 0; j < CPL; ++j)
                    if ((c[j] >> b) == (p >> b)) m = max(m, c[j]);
                T = __reduce_max_sync(0xffffffffu, m);
                uint32_t e = 0;
#pragma unroll
                for (int j = 0; j < CPL; ++j) e += (c[j] == T) ? 1u : 0u;
                cntEq = __reduce_add_sync(0xffffffffu, e);
                need  = 1u;
                break;
            }
            --b;
            const uint32_t hi = (p >> b) | 1u;
            uint32_t cnt = 0;
#pragma unroll
            for (int j = 0; j < CPL; ++j) cnt += ((c[j] >> b) == hi) ? 1u : 0u;
            cnt = __reduce_add_sync(0xffffffffu, cnt);
            if (cnt >= kk) { p |= (1u << b); g = cnt; }
            else           { kk -= cnt;      g -= cnt; }
            if (b == 0) { T = p; need = kk; cntEq = g; break; }
        }
    } else {
        // ── exact fallback (~never taken): bisect over full row from global ──
        uint32_t p = 0u, kk = KSEL, g = (uint32_t)DDIM;
        for (int b = 30; b >= 0; --b) {
            const uint32_t hi = (p >> b) | 1u;
            uint32_t cnt = 0;
            for (int i = 0; i < NCHUNK; ++i) {
                const float4 v = xr[i * 32 + lane];
                cnt += ((absbits(v.x) >> b) == hi) ? 1u : 0u;
                cnt += ((absbits(v.y) >> b) == hi) ? 1u : 0u;
                cnt += ((absbits(v.z) >> b) == hi) ? 1u : 0u;
                cnt += ((absbits(v.w) >> b) == hi) ? 1u : 0u;
            }
            cnt = __reduce_add_sync(0xffffffffu, cnt);
            if (cnt >= kk) { p |= (1u << b); g = cnt; }
            else           { kk -= cnt;      g -= cnt; }
        }
        T = p; need = kk; cntEq = g;
    }

    const bool rare = (need != cntEq);            // warp-uniform
    const float SCALE = (float)(2048.0 / 204.0);

    if (fastok && !rare) {
        // ── Pass C fast: zero-fill + scatter from smem; no global re-read ──
        const float4 z4 = make_float4(0.0f, 0.0f, 0.0f, 0.0f);
#pragma unroll 4
        for (int i = 0; i < NCHUNK; ++i) __stcs(&orow[i * 32 + lane], z4);
        __syncwarp();                             // order zero-fill before scatter (warp-private row)
        float* __restrict__ op = reinterpret_cast<float*>(orow);
#pragma unroll
        for (int j = 0; j < CPL; ++j) {
            const uint32_t sidx = (uint32_t)lane + 32u * j;
            if (sidx < nc) {
                const uint32_t raw = wraw[sidx];
                if ((raw & 0x7fffffffu) >= T)
                    op[widx[sidx]] = __uint_as_float(raw) * SCALE;
            }
        }
    } else {
        // ── Pass C slow: global re-read (exact for ties / fallback) ──
        const float Tf = __uint_as_float(T);      // positive; |v|>=Tf <=> absbits(v)>=T
        if (!rare) {
#pragma unroll 4
            for (int i = 0; i < NCHUNK; ++i) {
                const float4 v = xr[i * 32 + lane];
                float4 o;
                o.x = (fabsf(v.x) >= Tf) ? v.x * SCALE : 0.0f;
                o.y = (fabsf(v.y) >= Tf) ? v.y * SCALE : 0.0f;
                o.z = (fabsf(v.z) >= Tf) ? v.z * SCALE : 0.0f;
                o.w = (fabsf(v.w) >= Tf) ? v.w * SCALE : 0.0f;
                __stcs(&orow[i * 32 + lane], o);
            }
        } else {
            // exact lowest-index-first tie ranking (index = i*128 + lane*4 + j)
            uint32_t run = 0;
#pragma unroll 4
            for (int i = 0; i < NCHUNK; ++i) {
                const float4 v = xr[i * 32 + lane];
                const uint32_t k0 = absbits(v.x), k1 = absbits(v.y),
                               k2 = absbits(v.z), k3 = absbits(v.w);
                const uint32_t e0 = (k0 == T), e1 = (k1 == T),
                               e2 = (k2 == T), e3 = (k3 == T);
                uint32_t elane = e0 + e1 + e2 + e3;
                uint32_t incl = elane;
#pragma unroll
                for (int off = 1; off < 32; off <<= 1) {
                    const uint32_t t = __shfl_up_sync(0xffffffffu, incl, off);
                    if (lane >= off) incl += t;
                }
                uint32_t r = run + (incl - elane);
                float4 o;
                o.x = ((k0 > T) || (e0 && r < need)) ? v.x * SCALE : 0.0f; r += e0;
                o.y = ((k1 > T) || (e1 && r < need)) ? v.y * SCALE : 0.0f; r += e1;
                o.z = ((k2 > T) || (e2 && r < need)) ? v.z * SCALE : 0.0f; r += e2;
                o.w = ((k3 > T) || (e3 && r < need)) ? v.w * SCALE : 0.0f;
                run += __shfl_sync(0xffffffffu, incl, 31);
                __stcs(&orow[i * 32 + lane], o);
            }
        }
    }
}

extern "C" void kernel_launch(void* const* d_in, const int* in_sizes, int n_in,
                              void* d_out, int out_size)
{
    const float* x = (const float*)d_in[0];
    float* out = (float*)d_out;
    const int rows   = in_sizes[0] / DDIM;            // 16384
    const int blocks = rows / WARPS_PER_CTA;          // 2048
    sparse_act_kernel<<<blocks, THREADS>>>(x, out);
}

// round 14
// speedup vs baseline: 1.1073x; 1.1073x over previous
#include <cuda_runtime.h>
#include <stdint.h>

// SparseActivation: per-row top-k (k=204) by |x| over D=2048, out = x*mask*(D/k).
// ONE WARP PER ROW, no __syncthreads. (R11 skeleton + min-blocks=4 clamp, the
// annotation proven safe in R4: regs<=64 -> 4 CTAs/SM -> 32 resident warps.)
//  Pass A: 16 LDG.128/lane (unroll 8); ballot-compact RAW float bits of
//          |v|>=1.45f into a per-warp smem buffer (E[nc]~300+-16; checked vs [204,416]).
//  Pass B: warp-local MSB-first bisection over <=13 register-resident candidates
//          (abs-masked at load), early exit (rank==group -> min, rank==1 -> max),
//          REDUX reductions. Out-of-range nc -> exact global-bisect fallback.
//  Pass C: re-read row (L2 hot, unroll 4); common path float compare |v|>=T_f
//          (bit-exact == integer compare on abs bits for non-NaN); rare bit-tie
//          path exact lowest-index-first ranking. Streaming stores.

#define DDIM          2048
#define KSEL          204u
#define WARPS_PER_CTA 8
#define THREADS       (WARPS_PER_CTA * 32)
#define NCHUNK        16          // 16 float4 per lane = 2048 floats per warp
#define CAP           416         // per-warp candidate cap = 13 per lane
#define CPL           13
#define KLO_F         1.45f

static __device__ __forceinline__ uint32_t absbits(float f) {
    return __float_as_uint(f) & 0x7fffffffu;
}

__global__ __launch_bounds__(THREADS, 4)
void sparse_act_kernel(const float* __restrict__ x, float* __restrict__ out)
{
    __shared__ uint32_t buf[WARPS_PER_CTA][CAP];

    const int lane = threadIdx.x & 31;
    const int warp = threadIdx.x >> 5;
    const size_t row = (size_t)blockIdx.x * WARPS_PER_CTA + warp;

    const float4* __restrict__ xr   = reinterpret_cast<const float4*>(x + row * (size_t)DDIM);
    float4* __restrict__       orow = reinterpret_cast<float4*>(out + row * (size_t)DDIM);
    uint32_t* __restrict__     wbuf = buf[warp];

    // ── Pass A: ballot-compact raw bits of candidates (|v| >= KLO_F) ──
    uint32_t base = 0;
#pragma unroll 8
    for (int i = 0; i < NCHUNK; ++i) {
        const float4 v = xr[i * 32 + lane];
        const float vv[4] = { v.x, v.y, v.z, v.w };
#pragma unroll
        for (int j = 0; j < 4; ++j) {
            const bool p = fabsf(vv[j]) >= KLO_F;
            const uint32_t bal = __ballot_sync(0xffffffffu, p);
            const uint32_t off = base + (uint32_t)__popc(bal & ((1u << lane) - 1u));
            if (p && off < CAP) wbuf[off] = __float_as_uint(vv[j]);   // raw bits
            base += (uint32_t)__popc(bal);
        }
    }
    const uint32_t nc = base;

    uint32_t T, need, cntEq;

    if (nc >= KSEL && nc <= CAP) {
        // ── Pass B (fast): register-resident candidates, early-exit bisection ──
        uint32_t c[CPL];
#pragma unroll
        for (int j = 0; j < CPL; ++j) {
            const uint32_t idx = (uint32_t)lane + 32u * j;   // < CAP always
            const uint32_t t = wbuf[idx] & 0x7fffffffu;      // abs-mask here
            c[j] = (idx < nc) ? t : 0xffffffffu;             // sentinel (never matches)
        }
        int b = 31;
        uint32_t p = 0u, kk = KSEL, g = nc;
        while (true) {
            if (kk == g) {            // take whole group -> T = group min
                uint32_t m = 0xffffffffu;
#pragma unroll
                for (int j = 0; j < CPL; ++j)
                    if ((c[j] >> b) == (p >> b)) m = min(m, c[j]);
                T = __reduce_min_sync(0xffffffffu, m);
                uint32_t e = 0;
#pragma unroll
                for (int j = 0; j < CPL; ++j) e += (c[j] == T) ? 1u : 0u;
                need  = __reduce_add_sync(0xffffffffu, e);
                cntEq = need;
                break;
            }
            if (kk == 1u) {           // T = group max
                uint32_t m = 0u;
#pragma unroll
                for (int j = 0; j < CPL; ++j)
                    if ((c[j] >> b) == (p >> b)) m = max(m, c[j]);
                T = __reduce_max_sync(0xffffffffu, m);
                uint32_t e = 0;
#pragma unroll
                for (int j = 0; j < CPL; ++j) e += (c[j] == T) ? 1u : 0u;
                cntEq = __reduce_add_sync(0xffffffffu, e);
                need  = 1u;
                break;
            }
            --b;
            const uint32_t hi = (p >> b) | 1u;
            uint32_t cnt = 0;
#pragma unroll
            for (int j = 0; j < CPL; ++j) cnt += ((c[j] >> b) == hi) ? 1u : 0u;
            cnt = __reduce_add_sync(0xffffffffu, cnt);
            if (cnt >= kk) { p |= (1u << b); g = cnt; }
            else           { kk -= cnt;      g -= cnt; }
            if (b == 0) { T = p; need = kk; cntEq = g; break; }
        }
    } else {
        // ── exact fallback (~never taken): bisect over full row from global ──
        uint32_t p = 0u, kk = KSEL, g = (uint32_t)DDIM;
        for (int b = 30; b >= 0; --b) {
            const uint32_t hi = (p >> b) | 1u;
            uint32_t cnt = 0;
            for (int i = 0; i < NCHUNK; ++i) {
                const float4 v = xr[i * 32 + lane];
                cnt += ((absbits(v.x) >> b) == hi) ? 1u : 0u;
                cnt += ((absbits(v.y) >> b) == hi) ? 1u : 0u;
                cnt += ((absbits(v.z) >> b) == hi) ? 1u : 0u;
                cnt += ((absbits(v.w) >> b) == hi) ? 1u : 0u;
            }
            cnt = __reduce_add_sync(0xffffffffu, cnt);
            if (cnt >= kk) { p |= (1u << b); g = cnt; }
            else           { kk -= cnt;      g -= cnt; }
        }
        T = p; need = kk; cntEq = g;
    }

    const bool rare = (need != cntEq);            // warp-uniform
    const float Tf  = __uint_as_float(T);         // positive; |v|>=Tf <=> absbits(v)>=T
    const float SCALE = (float)(2048.0 / 204.0);

    // ── Pass C: re-read (L2 hot), mask, scale, streaming store ──
    if (!rare) {
#pragma unroll 4
        for (int i = 0; i < NCHUNK; ++i) {
            const float4 v = xr[i * 32 + lane];
            float4 o;
            o.x = (fabsf(v.x) >= Tf) ? v.x * SCALE : 0.0f;
            o.y = (fabsf(v.y) >= Tf) ? v.y * SCALE : 0.0f;
            o.z = (fabsf(v.z) >= Tf) ? v.z * SCALE : 0.0f;
            o.w = (fabsf(v.w) >= Tf) ? v.w * SCALE : 0.0f;
            __stcs(&orow[i * 32 + lane], o);
        }
    } else {
        // exact lowest-index-first tie ranking (index = i*128 + lane*4 + j)
        uint32_t run = 0;
#pragma unroll 4
        for (int i = 0; i < NCHUNK; ++i) {
            const float4 v = xr[i * 32 + lane];
            const uint32_t k0 = absbits(v.x), k1 = absbits(v.y),
                           k2 = absbits(v.z), k3 = absbits(v.w);
            const uint32_t e0 = (k0 == T), e1 = (k1 == T),
                           e2 = (k2 == T), e3 = (k3 == T);
            uint32_t elane = e0 + e1 + e2 + e3;
            uint32_t incl = elane;
#pragma unroll
            for (int off = 1; off < 32; off <<= 1) {
                const uint32_t t = __shfl_up_sync(0xffffffffu, incl, off);
                if (lane >= off) incl += t;
            }
            uint32_t r = run + (incl - elane);
            float4 o;
            o.x = ((k0 > T) || (e0 && r < need)) ? v.x * SCALE : 0.0f; r += e0;
            o.y = ((k1 > T) || (e1 && r < need)) ? v.y * SCALE : 0.0f; r += e1;
            o.z = ((k2 > T) || (e2 && r < need)) ? v.z * SCALE : 0.0f; r += e2;
            o.w = ((k3 > T) || (e3 && r < need)) ? v.w * SCALE : 0.0f;
            run += __shfl_sync(0xffffffffu, incl, 31);
            __stcs(&orow[i * 32 + lane], o);
        }
    }
}

extern "C" void kernel_launch(void* const* d_in, const int* in_sizes, int n_in,
                              void* d_out, int out_size)
{
    const float* x = (const float*)d_in[0];
    float* out = (float*)d_out;
    const int rows   = in_sizes[0] / DDIM;            // 16384
    const int blocks = rows / WARPS_PER_CTA;          // 2048
    sparse_act_kernel<<<blocks, THREADS>>>(x, out);
}